// round 16
// baseline (speedup 1.0000x reference)
#include <cuda_runtime.h>
#include <cuda_bf16.h>
#include <cstdint>
#include <math.h>

// ---------------- problem constants ----------------
#define N_IMG 2
#define R_TOT 159882
#define N_LVL 5
#define N_IL  (N_IMG * N_LVL)
#define POST_NMS 1000
#define NMS_THRESH 0.7f
#define IMG_MAX 800.0f
#define MIN_SIZE 1e-3f
#define BBOX_CLIP 4.135166556742356f   // log(1000/16) rounded to f32
#define COLLCAP 2048                   // 12-bit superset max ~1.5k for L0
#define BLK_PER_IMG 72                 // 48+12+4+4+4
#define GRID_TOT (N_IMG * BLK_PER_IMG) // 144 <= 148 SMs, co-resident
#define DYN_BYTES 131072               // 128KB: mask copy; aliased by all phases

__constant__ int c_loff[N_LVL]  = {0, 120000, 150000, 157500, 159375};
__constant__ int c_lsize[N_LVL] = {120000, 30000, 7500, 1875, 507};
__constant__ int c_ksel[N_LVL]  = {1000, 1000, 1000, 1000, 507};
__constant__ int c_nblk[N_LVL]  = {48, 12, 4, 4, 4};

// ---------------- scratch (device globals; zero-initialized at load) --------
__device__ unsigned           g_hist[N_IL * 4096];   // zeroed by select
__device__ int                g_tkA[N_IL], g_tkB[N_IL], g_tkD[N_IL], g_tkE[N_IMG];
__device__ int                g_phaseA[N_IL], g_consA[N_IL];
__device__ int                g_phaseC[N_IL], g_consC[N_IL];
__device__ unsigned           g_T[N_IL];
__device__ int                g_ccnt[N_IL];
__device__ unsigned long long g_coll[N_IL * COLLCAP];
__device__ int                g_ncnt[N_IL];
__device__ float4             g_nbox [N_IL * 1024];   // OFFSET boxes
__device__ float              g_narea[N_IL * 1024];
__device__ unsigned long long g_nkey [N_IL * 1024];
__device__ int                g_npos [N_IL * 1024];
__device__ float4             g_rawbox[N_IL * 1024];
__device__ float              g_rawsc [N_IL * 1024];
// suppression bit-matrix as u64 words: [il][w64][i], w64 < 16
__device__ unsigned long long g_mask64[N_IL * 16 * 1024];
__device__ unsigned long long g_kept_key[N_IL * 1024];
__device__ int                g_kept_p  [N_IL * 1024];
__device__ int                g_kept_cnt[N_IL];

// ---------------- helpers ----------------
__device__ __forceinline__ unsigned mono_key(float f) {
    unsigned u = __float_as_uint(f);
    return (u & 0x80000000u) ? ~u : (u | 0x80000000u);
}
__device__ __forceinline__ float mono_inv(unsigned m) {
    unsigned u = (m & 0x80000000u) ? (m & 0x7fffffffu) : ~m;
    return __uint_as_float(u);
}

__device__ __forceinline__ int block_scan_flag(bool flag, int* total) {
    __shared__ int wsum[32];
    int lane = threadIdx.x & 31;
    int wid  = threadIdx.x >> 5;
    unsigned ballot = __ballot_sync(0xffffffffu, flag);
    int lane_pref = __popc(ballot & ((1u << lane) - 1u));
    if (lane == 0) wsum[wid] = __popc(ballot);
    __syncthreads();
    if (wid == 0) {
        int v = wsum[lane];
        #pragma unroll
        for (int d = 1; d < 32; d <<= 1) {
            int x = __shfl_up_sync(0xffffffffu, v, d);
            if (lane >= d) v += x;
        }
        wsum[lane] = v;
    }
    __syncthreads();
    int excl = (wid == 0 ? 0 : wsum[wid - 1]) + lane_pref;
    *total = wsum[31];
    __syncthreads();
    return excl;
}

// release flag; each of nblk passers consumes; last consumer resets both.
__device__ __forceinline__ void flag_release_and_consume(int* flag, int* cons, int nblk) {
    atomicExch(flag, 1);
    if (atomicAdd(cons, 1) == nblk - 1) { *cons = 0; atomicExch(flag, 0); }
}
__device__ __forceinline__ void flag_wait_and_consume(int* flag, int* cons, int nblk) {
    while (atomicAdd(flag, 0) == 0) {}
    if (atomicAdd(cons, 1) == nblk - 1) { *cons = 0; atomicExch(flag, 0); }
}

// ============ THE kernel: all phases, one launch ==============================
// 144 blocks x 1024 threads, 128KB dyn smem -> 1 block/SM, all co-resident.
__global__ void __launch_bounds__(1024, 1)
rpn_kernel(const float* __restrict__ obj,
           const float* __restrict__ deltas,
           const float* __restrict__ anchors,
           float* __restrict__ out) {
    extern __shared__ char dyn[];
    // block -> (img, lvl, b, nblk); per image: L0:48, L1:12, L2:4, L3:4, L4:4
    const int bi  = blockIdx.x;
    const int img = bi / BLK_PER_IMG;
    const int r0_ = bi % BLK_PER_IMG;
    int lvl, b;
    if      (r0_ < 48) { lvl = 0; b = r0_; }
    else if (r0_ < 60) { lvl = 1; b = r0_ - 48; }
    else if (r0_ < 64) { lvl = 2; b = r0_ - 60; }
    else if (r0_ < 68) { lvl = 3; b = r0_ - 64; }
    else               { lvl = 4; b = r0_ - 68; }
    const int nblk = c_nblk[lvl];
    const int il   = img * N_LVL + lvl;

    const int tid = threadIdx.x;
    const int lane = tid & 31;
    const int wrp  = tid >> 5;
    const int n    = c_lsize[lvl];
    const int base = c_loff[lvl];
    const int k    = c_ksel[lvl];
    const int chunk = (n + nblk - 1) / nblk;
    const int i0 = min(b * chunk, n);
    const int i1 = min(i0 + chunk, n);
    const float* src = obj + img * R_TOT + base;
    const bool small_lvl = (n <= COLLCAP);   // L3, L4: whole level fits buffer

    // ================= Phase A: 12-bit histogram (skipped for small levels) ====
    if (!small_lvl) {
        unsigned* hist = (unsigned*)dyn;                 // 16KB
        for (int t = tid; t < 4096; t += 1024) hist[t] = 0;
        __syncthreads();
        for (int i = i0 + tid; i < i1; i += 1024)
            atomicAdd(&hist[mono_key(src[i]) >> 20], 1u);
        __syncthreads();
        unsigned* gh = &g_hist[il * 4096];
        for (int t = tid; t < 4096; t += 1024)
            if (hist[t]) atomicAdd(&gh[t], hist[t]);
        __threadfence();

        __shared__ int s_last;
        if (tid == 0) {
            int t1 = atomicAdd(&g_tkA[il], 1);
            s_last = (t1 == nblk - 1);
            if (s_last) g_tkA[il] = 0;
        }
        __syncthreads();
        if (s_last) {
            __threadfence();
            __shared__ unsigned wtot[32], wtot2[32];
            __shared__ unsigned sh_bstar;
            const unsigned kth = (unsigned)k;
            unsigned e[4];
            const int bb = tid * 4;
            #pragma unroll
            for (int j = 0; j < 4; ++j) { e[j] = gh[bb + j]; gh[bb + j] = 0u; }
            unsigned s = e[0] + e[1] + e[2] + e[3];
            unsigned S = s;
            #pragma unroll
            for (int d = 1; d < 32; d <<= 1) {
                unsigned x = __shfl_down_sync(0xffffffffu, S, d);
                if (lane + d < 32) S += x;
            }
            if (lane == 0) wtot[wrp] = S;
            __syncthreads();
            if (wrp == 0) {
                unsigned W = wtot[lane];
                #pragma unroll
                for (int d = 1; d < 32; d <<= 1) {
                    unsigned x = __shfl_down_sync(0xffffffffu, W, d);
                    if (lane + d < 32) W += x;
                }
                wtot2[lane] = W;
            }
            __syncthreads();
            const unsigned after_warp = (wrp < 31) ? wtot2[wrp + 1] : 0u;
            unsigned suf = (S - s) + after_warp;
            #pragma unroll
            for (int j = 3; j >= 0; --j) {
                unsigned sufnext = suf;
                suf += e[j];
                if (suf >= kth && sufnext < kth) sh_bstar = (unsigned)(bb + j);
            }
            __syncthreads();
            if (tid == 0) {
                g_T[il] = sh_bstar << 20;
                g_ccnt[il] = 0;
                __threadfence();
                flag_release_and_consume(&g_phaseA[il], &g_consA[il], nblk);
            }
        } else {
            if (tid == 0) flag_wait_and_consume(&g_phaseA[il], &g_consA[il], nblk);
        }
        __syncthreads();
        __threadfence();
    }

    // ================= Phase B: collect superset (warp-aggregated) =============
    const unsigned T = small_lvl ? 0u : g_T[il];   // small level: take all
    for (int bs2 = i0; bs2 < i1; bs2 += 1024) {
        const int i = bs2 + tid;
        bool take = false;
        unsigned u = 0;
        if (i < i1) {
            u = mono_key(src[i]);
            take = (u >= T);
        }
        unsigned ball = __ballot_sync(0xffffffffu, take);
        if (ball) {
            const int leader = __ffs(ball) - 1;
            const int cnt2 = __popc(ball);
            int basep = 0;
            if (lane == leader) basep = atomicAdd(&g_ccnt[il], cnt2);
            basep = __shfl_sync(0xffffffffu, basep, leader);
            if (take) {
                int p = basep + __popc(ball & ((1u << lane) - 1u));
                if (p < COLLCAP)
                    g_coll[il * COLLCAP + p] = ((unsigned long long)u << 17) | (unsigned)(131071 - i);
            }
        }
    }
    __threadfence();
    __shared__ int s_lastB;
    if (tid == 0) {
        int t2 = atomicAdd(&g_tkB[il], 1);
        s_lastB = (t2 == nblk - 1);
        if (s_lastB) g_tkB[il] = 0;
    }
    __syncthreads();

    if (s_lastB) {
        __threadfence();
        // ---- Phase C: hybrid register/smem bitonic sort + decode + compact ----
        unsigned long long* skey = (unsigned long long*)dyn;   // 16KB
        const int csel = min(g_ccnt[il], COLLCAP);
        for (int t = tid; t < COLLCAP; t += 1024)
            skey[t] = (t < csel) ? g_coll[il * COLLCAP + t] : 0ull;
        __syncthreads();

        int sortN = 512;
        while (sortN < csel) sortN <<= 1;   // <= 2048
        const int span_w = sortN >> 6;      // warps holding a 64-elem span

        for (int k2 = 2; k2 <= sortN; k2 <<= 1) {
            // smem stages: j >= 64
            for (int j = k2 >> 1; j >= 64; j >>= 1) {
                if (tid < (sortN >> 1)) {
                    int i2 = ((tid & ~(j - 1)) << 1) | (tid & (j - 1));
                    int p2 = i2 + j;
                    bool dir = ((i2 & k2) == 0);
                    unsigned long long A = skey[i2], B = skey[p2];
                    if ((A > B) == dir) { skey[i2] = B; skey[p2] = A; }
                }
                __syncthreads();
            }
            // register stages: j = min(k2/2, 32) .. 1 (warp-local, no barriers)
            if (wrp < span_w) {
                const int ib0 = (wrp << 6) + lane;       // element index of e0
                const int ib1 = ib0 + 32;                // element index of e1
                unsigned long long e0 = skey[ib0];
                unsigned long long e1 = skey[ib1];
                const int jstart = ((k2 >> 1) < 32) ? (k2 >> 1) : 32;
                for (int j = jstart; j > 0; j >>= 1) {
                    if (j == 32) {
                        bool dir = ((ib0 & k2) == 0);    // k2 >= 64 here: same for both
                        if ((e0 > e1) == dir) { unsigned long long t2 = e0; e0 = e1; e1 = t2; }
                    } else {
                        unsigned long long o0 = __shfl_xor_sync(0xffffffffu, e0, j);
                        unsigned long long o1 = __shfl_xor_sync(0xffffffffu, e1, j);
                        const bool low = (lane & j) == 0;
                        const bool dir0 = ((ib0 & k2) == 0);
                        const bool dir1 = ((ib1 & k2) == 0);
                        unsigned long long mn0 = (e0 < o0) ? e0 : o0;
                        unsigned long long mx0 = (e0 < o0) ? o0 : e0;
                        unsigned long long mn1 = (e1 < o1) ? e1 : o1;
                        unsigned long long mx1 = (e1 < o1) ? o1 : e1;
                        e0 = (dir0 == low) ? mn0 : mx0;
                        e1 = (dir1 == low) ? mn1 : mx1;
                    }
                }
                skey[ib0] = e0;
                skey[ib1] = e1;
            }
            __syncthreads();
        }

        bool flag = false;
        float4 obox = make_float4(0.f, 0.f, 0.f, 0.f);
        float area = 0.f, score = 0.f;
        if (tid < k) {
            unsigned long long kk = skey[sortN - 1 - tid];
            int i = 131071 - (int)(kk & 0x1FFFFull);
            int r = base + i;
            const float o = mono_inv((unsigned)(kk >> 17));
            score = __fdiv_rn(1.0f, __fadd_rn(1.0f, expf(-o)));

            float4 a = *(const float4*)(anchors + 4 * r);
            const float wa = __fsub_rn(a.z, a.x);
            const float ha = __fsub_rn(a.w, a.y);
            const float cxa = __fadd_rn(a.x, __fmul_rn(0.5f, wa));
            const float cya = __fadd_rn(a.y, __fmul_rn(0.5f, ha));

            float4 d = *(const float4*)(deltas + (size_t)(img * R_TOT + r) * 4);
            const float dw = fminf(d.z, BBOX_CLIP);
            const float dh = fminf(d.w, BBOX_CLIP);
            const float cx = __fadd_rn(__fmul_rn(d.x, wa), cxa);
            const float cy = __fadd_rn(__fmul_rn(d.y, ha), cya);
            const float w = __fmul_rn(expf(dw), wa);
            const float h = __fmul_rn(expf(dh), ha);

            float x1 = __fsub_rn(cx, __fmul_rn(0.5f, w));
            float y1 = __fsub_rn(cy, __fmul_rn(0.5f, h));
            float x2 = __fadd_rn(cx, __fmul_rn(0.5f, w));
            float y2 = __fadd_rn(cy, __fmul_rn(0.5f, h));
            x1 = fminf(fmaxf(x1, 0.0f), IMG_MAX);
            y1 = fminf(fmaxf(y1, 0.0f), IMG_MAX);
            x2 = fminf(fmaxf(x2, 0.0f), IMG_MAX);
            y2 = fminf(fmaxf(y2, 0.0f), IMG_MAX);

            flag = (__fsub_rn(x2, x1) >= MIN_SIZE) &&
                   (__fsub_rn(y2, y1) >= MIN_SIZE) &&
                   (score >= 0.0f);
            g_rawbox[il * 1024 + tid] = make_float4(x1, y1, x2, y2);
            g_rawsc [il * 1024 + tid] = score;

            const float off = (float)lvl * 801.0f;
            float ox1 = __fadd_rn(x1, off);
            float oy1 = __fadd_rn(y1, off);
            float ox2 = __fadd_rn(x2, off);
            float oy2 = __fadd_rn(y2, off);
            obox = make_float4(ox1, oy1, ox2, oy2);
            area = __fmul_rn(__fsub_rn(ox2, ox1), __fsub_rn(oy2, oy1));
        }
        int m0;
        int pos = block_scan_flag(flag, &m0);
        if (flag) {
            const int gb = il * 1024 + pos;
            g_nbox [gb] = obox;
            g_narea[gb] = area;
            const int gpos = lvl * 1000 + tid;
            g_nkey [gb] = ((unsigned long long)mono_key(score) << 13) | (unsigned)(8191 - gpos);
            g_npos [gb] = tid;
        }
        if (tid == 0) g_ncnt[il] = m0;
        __threadfence();
        __syncthreads();
        if (tid == 0) flag_release_and_consume(&g_phaseC[il], &g_consC[il], nblk);
    } else {
        if (tid == 0) flag_wait_and_consume(&g_phaseC[il], &g_consC[il], nblk);
    }
    __syncthreads();
    __threadfence();

    // ================= Phase D: build bit-matrix (all nblk blocks) ==============
    float4* sbox  = (float4*)dyn;            // 16KB
    float*  sarea = (float*)(dyn + 16384);   // 4KB
    const int m = g_ncnt[il];
    for (int i = tid; i < m; i += 1024) {
        sbox[i]  = g_nbox [il * 1024 + i];
        sarea[i] = g_narea[il * 1024 + i];
    }
    __syncthreads();

    const int nch32 = (m + 31) >> 5;
    const int W64   = (nch32 + 1) >> 1;
    unsigned long long* gm64 = &g_mask64[il * 16384];
    for (int i = b * 32 + wrp; i < m; i += nblk * 32) {
        const float4 bi2 = sbox[i];
        const float ai = sarea[i];
        for (int w = (i >> 6) << 1; w < nch32; ++w) {
            const int j = (w << 5) + lane;
            bool sup = false;
            if (j > i && j < m) {
                float4 bj = sbox[j];
                float lx = fmaxf(bi2.x, bj.x), ly = fmaxf(bi2.y, bj.y);
                float rx = fminf(bi2.z, bj.z), ry = fminf(bi2.w, bj.w);
                float wx = fmaxf(__fsub_rn(rx, lx), 0.0f);
                float wy = fmaxf(__fsub_rn(ry, ly), 0.0f);
                float inter = __fmul_rn(wx, wy);
                if (inter > 0.0f) {
                    float denom = __fadd_rn(__fsub_rn(__fadd_rn(ai, sarea[j]), inter), 1e-9f);
                    float iou = __fdiv_rn(inter, denom);
                    sup = iou > NMS_THRESH;
                }
            }
            unsigned bits = __ballot_sync(0xffffffffu, sup);
            if (lane == 0) {
                unsigned* hw = (unsigned*)&gm64[(w >> 1) * 1024 + i];
                hw[w & 1] = bits;
            }
        }
    }
    __threadfence();
    __shared__ int s_lastD;
    if (tid == 0) {
        int t3 = atomicAdd(&g_tkD[il], 1);
        s_lastD = (t3 == nblk - 1);
        if (s_lastD) g_tkD[il] = 0;
    }
    __syncthreads();
    if (!s_lastD) return;
    __threadfence();

    // ================= Phase E: resolve (this block; mask in SMEM, 64-chunks) ===
    unsigned long long* sm = (unsigned long long*)dyn;   // [16][1024] = 128KB
    for (int t = tid; t < W64 * 1024; t += 1024) sm[t] = gm64[t];
    __shared__ unsigned long long ssup[16];
    __shared__ unsigned long long skept[16];
    if (tid < 16) { ssup[tid] = 0ull; skept[tid] = 0ull; }
    __syncthreads();

    for (int c = 0; c < W64; ++c) {
        if (tid == 0) {
            unsigned long long sup = ssup[c];
            unsigned long long kept = 0ull;
            const int jmax = min(64, m - (c << 6));
            const unsigned long long* dp = &sm[c * 1024 + (c << 6)];
            for (int g = 0; g < jmax; g += 8) {
                unsigned long long d0 = dp[g+0], d1 = dp[g+1], d2 = dp[g+2], d3 = dp[g+3];
                unsigned long long d4 = dp[g+4], d5 = dp[g+5], d6 = dp[g+6], d7 = dp[g+7];
                #pragma unroll
                for (int j2 = 0; j2 < 8; ++j2) {
                    const int j = g + j2;
                    if (j < jmax && !((sup >> j) & 1ull)) {
                        kept |= 1ull << j;
                        unsigned long long dj;
                        switch (j2) {
                            case 0: dj = d0; break; case 1: dj = d1; break;
                            case 2: dj = d2; break; case 3: dj = d3; break;
                            case 4: dj = d4; break; case 5: dj = d5; break;
                            case 6: dj = d6; break; default: dj = d7; break;
                        }
                        sup |= dj;
                    }
                }
            }
            skept[c] = kept;
        }
        __syncthreads();
        const int wfut = c + 1 + wrp;
        if (wfut < W64) {
            const unsigned long long kept = skept[c];
            unsigned long long v = 0ull;
            const int r1 = lane, r2 = lane + 32;
            if ((kept >> r1) & 1ull) v  = sm[wfut * 1024 + (c << 6) + r1];
            if ((kept >> r2) & 1ull) v |= sm[wfut * 1024 + (c << 6) + r2];
            #pragma unroll
            for (int d = 16; d > 0; d >>= 1)
                v |= __shfl_down_sync(0xffffffffu, v, d);
            if (lane == 0) ssup[wfut] |= v;
        }
        __syncthreads();
    }

    bool kf = (tid < m) && ((skept[tid >> 6] >> (tid & 63)) & 1ull);
    int mkept;
    int kpos = block_scan_flag(kf, &mkept);
    if (kf) {
        g_kept_key[il * 1024 + kpos] = g_nkey[il * 1024 + tid];
        g_kept_p  [il * 1024 + kpos] = g_npos[il * 1024 + tid];
    }
    if (tid == 0) g_kept_cnt[il] = mkept;
    __threadfence();
    __syncthreads();

    __shared__ int s_lastE;
    if (tid == 0) {
        int t4 = atomicAdd(&g_tkE[img], 1);
        s_lastE = (t4 == N_LVL - 1);
        if (s_lastE) g_tkE[img] = 0;
    }
    __syncthreads();
    if (!s_lastE) return;
    __threadfence();

    // ================= Phase F: merge-rank + output (1 block/image) ============
    unsigned long long* skeys = (unsigned long long*)dyn;   // 40KB
    __shared__ int cnt[N_LVL];
    if (tid < N_LVL) cnt[tid] = g_kept_cnt[img * N_LVL + tid];
    __syncthreads();
    for (int l = 0; l < N_LVL; ++l)
        for (int i = tid; i < cnt[l]; i += 1024)
            skeys[l * 1024 + i] = g_kept_key[(img * N_LVL + l) * 1024 + i];
    __syncthreads();

    float* out_b = out + img * (POST_NMS * 4);
    float* out_s = out + N_IMG * POST_NMS * 4 + img * POST_NMS;
    for (int r = tid; r < POST_NMS; r += 1024) {
        out_b[r * 4 + 0] = 0.0f;
        out_b[r * 4 + 1] = 0.0f;
        out_b[r * 4 + 2] = 0.0f;
        out_b[r * 4 + 3] = 0.0f;
        out_s[r] = -1.0f;
    }
    __syncthreads();

    for (int l = 0; l < N_LVL; ++l) {
        const int c2 = cnt[l];
        for (int i = tid; i < c2; i += 1024) {
            const unsigned long long key = skeys[l * 1024 + i];
            int rank = i;
            #pragma unroll
            for (int L2 = 0; L2 < N_LVL; ++L2) {
                if (L2 == l) continue;
                const unsigned long long* a = &skeys[L2 * 1024];
                int lo = 0, hi = cnt[L2];
                while (lo < hi) {
                    int mid = (lo + hi) >> 1;
                    if (a[mid] > key) lo = mid + 1; else hi = mid;
                }
                rank += lo;
            }
            if (rank < POST_NMS) {
                const int p = g_kept_p[(img * N_LVL + l) * 1024 + i];
                float4 bx = g_rawbox[(img * N_LVL + l) * 1024 + p];
                out_b[rank * 4 + 0] = bx.x;
                out_b[rank * 4 + 1] = bx.y;
                out_b[rank * 4 + 2] = bx.z;
                out_b[rank * 4 + 3] = bx.w;
                out_s[rank] = g_rawsc[(img * N_LVL + l) * 1024 + p];
            }
        }
    }
}

// ---------------- launch -----------------------------------------------------
extern "C" void kernel_launch(void* const* d_in, const int* in_sizes, int n_in,
                              void* d_out, int out_size) {
    const float* objectness = (const float*)d_in[0];   // [2, 159882]
    const float* deltas     = (const float*)d_in[1];   // [2, 159882, 4]
    const float* anchors    = (const float*)d_in[2];   // [159882, 4]
    float* out = (float*)d_out;                        // boxes [2,1000,4] ++ scores [2,1000]

    cudaFuncSetAttribute(rpn_kernel, cudaFuncAttributeMaxDynamicSharedMemorySize, DYN_BYTES);
    rpn_kernel<<<GRID_TOT, 1024, DYN_BYTES>>>(objectness, deltas, anchors, out);
}

// round 17
// speedup vs baseline: 1.1436x; 1.1436x over previous
#include <cuda_runtime.h>
#include <cuda_bf16.h>
#include <cstdint>
#include <math.h>

// ---------------- problem constants ----------------
#define N_IMG 2
#define R_TOT 159882
#define N_LVL 5
#define N_IL  (N_IMG * N_LVL)
#define POST_NMS 1000
#define NMS_THRESH 0.7f
#define IMG_MAX 800.0f
#define MIN_SIZE 1e-3f
#define BBOX_CLIP 4.135166556742356f   // log(1000/16) rounded to f32
#define COLLCAP 2048                   // 12-bit superset max ~1.1k for L0
#define BLK_PER_IMG 72                 // 32+16+8+8+8
#define GRID_TOT (N_IMG * BLK_PER_IMG) // 144 <= 148 SMs, co-resident
#define DYN_BYTES 131072               // 128KB: mask copy; aliased by all phases
#define PD 32                          // pad sync vars to 128B (1 line each)

__constant__ int c_loff[N_LVL]  = {0, 120000, 150000, 157500, 159375};
__constant__ int c_lsize[N_LVL] = {120000, 30000, 7500, 1875, 507};
__constant__ int c_ksel[N_LVL]  = {1000, 1000, 1000, 1000, 507};
__constant__ int c_nblk[N_LVL]  = {32, 16, 8, 8, 8};

// ---------------- scratch (device globals; zero-initialized at load) --------
__device__ unsigned           g_hist[N_IL * 4096];   // zeroed by select
__device__ int                g_tkA[N_IL * PD], g_tkB[N_IL * PD];
__device__ int                g_tkD[N_IL * PD], g_tkE[N_IMG * PD];
__device__ int                g_phaseA[N_IL * PD], g_consA[N_IL * PD];
__device__ int                g_phaseC[N_IL * PD], g_consC[N_IL * PD];
__device__ int                g_ccnt[N_IL * PD];
__device__ unsigned           g_T[N_IL];
__device__ unsigned long long g_coll[N_IL * COLLCAP];
__device__ int                g_ncnt[N_IL];
__device__ float4             g_nbox [N_IL * 1024];   // OFFSET boxes
__device__ float              g_narea[N_IL * 1024];
__device__ unsigned long long g_nkey [N_IL * 1024];
__device__ int                g_npos [N_IL * 1024];
__device__ float4             g_rawbox[N_IL * 1024];
__device__ float              g_rawsc [N_IL * 1024];
// suppression bit-matrix as u64 words: [il][w64][i], w64 < 16
__device__ unsigned long long g_mask64[N_IL * 16 * 1024];
__device__ unsigned long long g_kept_key[N_IL * 1024];
__device__ int                g_kept_p  [N_IL * 1024];
__device__ int                g_kept_cnt[N_IL];

// ---------------- helpers ----------------
__device__ __forceinline__ unsigned mono_key(float f) {
    unsigned u = __float_as_uint(f);
    return (u & 0x80000000u) ? ~u : (u | 0x80000000u);
}
__device__ __forceinline__ float mono_inv(unsigned m) {
    unsigned u = (m & 0x80000000u) ? (m & 0x7fffffffu) : ~m;
    return __uint_as_float(u);
}

__device__ __forceinline__ int block_scan_flag(bool flag, int* total) {
    __shared__ int wsum[32];
    int lane = threadIdx.x & 31;
    int wid  = threadIdx.x >> 5;
    unsigned ballot = __ballot_sync(0xffffffffu, flag);
    int lane_pref = __popc(ballot & ((1u << lane) - 1u));
    if (lane == 0) wsum[wid] = __popc(ballot);
    __syncthreads();
    if (wid == 0) {
        int v = wsum[lane];
        #pragma unroll
        for (int d = 1; d < 32; d <<= 1) {
            int x = __shfl_up_sync(0xffffffffu, v, d);
            if (lane >= d) v += x;
        }
        wsum[lane] = v;
    }
    __syncthreads();
    int excl = (wid == 0 ? 0 : wsum[wid - 1]) + lane_pref;
    *total = wsum[31];
    __syncthreads();
    return excl;
}

// leader-only (tid==0) release/wait with consumption-reset. Caller must
// __syncthreads() BEFORE release (covers other threads' writes, CG pattern)
// and AFTER wait (broadcast + L1-invalidate ordering).
__device__ __forceinline__ void flag_release_and_consume(int* flag, int* cons, int nblk) {
    __threadfence();
    atomicExch(flag, 1);
    if (atomicAdd(cons, 1) == nblk - 1) { *cons = 0; atomicExch(flag, 0); }
}
__device__ __forceinline__ void flag_wait_and_consume(int* flag, int* cons, int nblk) {
    while (*(volatile int*)flag == 0) __nanosleep(64);
    __threadfence();
    if (atomicAdd(cons, 1) == nblk - 1) { *cons = 0; atomicExch(flag, 0); }
}

// ============ THE kernel: all phases, one launch ==============================
// 144 blocks x 1024 threads, 128KB dyn smem -> 1 block/SM, all co-resident.
__global__ void __launch_bounds__(1024, 1)
rpn_kernel(const float* __restrict__ obj,
           const float* __restrict__ deltas,
           const float* __restrict__ anchors,
           float* __restrict__ out) {
    extern __shared__ char dyn[];
    const int bi  = blockIdx.x;
    const int img = bi / BLK_PER_IMG;
    const int r0_ = bi % BLK_PER_IMG;
    int lvl, b;
    if      (r0_ < 32) { lvl = 0; b = r0_; }
    else if (r0_ < 48) { lvl = 1; b = r0_ - 32; }
    else if (r0_ < 56) { lvl = 2; b = r0_ - 48; }
    else if (r0_ < 64) { lvl = 3; b = r0_ - 56; }
    else               { lvl = 4; b = r0_ - 64; }
    const int nblk = c_nblk[lvl];
    const int il   = img * N_LVL + lvl;
    const int ilp  = il * PD;

    const int tid = threadIdx.x;
    const int lane = tid & 31;
    const int wrp  = tid >> 5;
    const int n    = c_lsize[lvl];
    const int base = c_loff[lvl];
    const int k    = c_ksel[lvl];
    const int chunk = (n + nblk - 1) / nblk;
    const int i0 = min(b * chunk, n);
    const int i1 = min(i0 + chunk, n);
    const float* src = obj + img * R_TOT + base;
    const bool small_lvl = (n <= COLLCAP);   // L3, L4: whole level fits buffer

    __shared__ int s_last;

    // ================= Phase A: 12-bit histogram (skipped for small levels) ====
    if (!small_lvl) {
        unsigned* hist = (unsigned*)dyn;                 // 16KB
        for (int t = tid; t < 4096; t += 1024) hist[t] = 0;
        __syncthreads();
        for (int i = i0 + tid; i < i1; i += 1024)
            atomicAdd(&hist[mono_key(src[i]) >> 20], 1u);
        __syncthreads();
        unsigned* gh = &g_hist[il * 4096];
        for (int t = tid; t < 4096; t += 1024)
            if (hist[t]) atomicAdd(&gh[t], hist[t]);
        __syncthreads();
        if (tid == 0) {
            __threadfence();
            int t1 = atomicAdd(&g_tkA[ilp], 1);
            s_last = (t1 == nblk - 1);
            if (s_last) g_tkA[ilp] = 0;
        }
        __syncthreads();
        if (s_last) {
            if (tid == 0) __threadfence();   // acquire all gh adds
            __syncthreads();
            __shared__ unsigned wtot[32], wtot2[32];
            __shared__ unsigned sh_bstar;
            const unsigned kth = (unsigned)k;
            unsigned e[4];
            const int bb = tid * 4;
            #pragma unroll
            for (int j = 0; j < 4; ++j) { e[j] = gh[bb + j]; gh[bb + j] = 0u; }
            unsigned s = e[0] + e[1] + e[2] + e[3];
            unsigned S = s;
            #pragma unroll
            for (int d = 1; d < 32; d <<= 1) {
                unsigned x = __shfl_down_sync(0xffffffffu, S, d);
                if (lane + d < 32) S += x;
            }
            if (lane == 0) wtot[wrp] = S;
            __syncthreads();
            if (wrp == 0) {
                unsigned W = wtot[lane];
                #pragma unroll
                for (int d = 1; d < 32; d <<= 1) {
                    unsigned x = __shfl_down_sync(0xffffffffu, W, d);
                    if (lane + d < 32) W += x;
                }
                wtot2[lane] = W;
            }
            __syncthreads();
            const unsigned after_warp = (wrp < 31) ? wtot2[wrp + 1] : 0u;
            unsigned suf = (S - s) + after_warp;
            #pragma unroll
            for (int j = 3; j >= 0; --j) {
                unsigned sufnext = suf;
                suf += e[j];
                if (suf >= kth && sufnext < kth) sh_bstar = (unsigned)(bb + j);
            }
            __syncthreads();
            if (tid == 0) {
                g_T[il] = sh_bstar << 20;
                g_ccnt[ilp] = 0;
                flag_release_and_consume(&g_phaseA[ilp], &g_consA[ilp], nblk);
            }
        } else {
            if (tid == 0) flag_wait_and_consume(&g_phaseA[ilp], &g_consA[ilp], nblk);
        }
        __syncthreads();
    }

    // ================= Phase B: collect superset ================================
    if (small_lvl) {
        // every element collected; position == element index (atomic-free)
        for (int i = i0 + tid; i < i1; i += 1024) {
            unsigned u = mono_key(src[i]);
            g_coll[il * COLLCAP + i] = ((unsigned long long)u << 17) | (unsigned)(131071 - i);
        }
    } else {
        const unsigned T = g_T[il];
        // pass 1: count this block's hits
        int myh = 0;
        for (int i = i0 + tid; i < i1; i += 1024)
            myh += (mono_key(src[i]) >= T) ? 1 : 0;
        __shared__ int red[32];
        int v = myh;
        #pragma unroll
        for (int d = 16; d > 0; d >>= 1) v += __shfl_down_sync(0xffffffffu, v, d);
        if (lane == 0) red[wrp] = v;
        __syncthreads();
        __shared__ int s_base;
        if (tid == 0) {
            int tot = 0;
            #pragma unroll
            for (int w = 0; w < 32; ++w) tot += red[w];
            s_base = atomicAdd(&g_ccnt[ilp], tot);   // ONE atomic per block
        }
        __syncthreads();
        // pass 2: ordered scatter via block scans
        int run = s_base;
        for (int bs2 = i0; bs2 < i1; bs2 += 1024) {
            const int i = bs2 + tid;
            bool take = false;
            unsigned u = 0;
            if (i < i1) {
                u = mono_key(src[i]);
                take = (u >= T);
            }
            int tot;
            int pos = block_scan_flag(take, &tot);
            if (take) {
                int p = run + pos;
                if (p < COLLCAP)
                    g_coll[il * COLLCAP + p] = ((unsigned long long)u << 17) | (unsigned)(131071 - i);
            }
            run += tot;
        }
    }
    __syncthreads();
    __shared__ int s_lastB;
    if (tid == 0) {
        __threadfence();
        int t2 = atomicAdd(&g_tkB[ilp], 1);
        s_lastB = (t2 == nblk - 1);
        if (s_lastB) g_tkB[ilp] = 0;
    }
    __syncthreads();

    if (s_lastB) {
        if (tid == 0) __threadfence();   // acquire g_coll / g_ccnt
        __syncthreads();
        // ---- Phase C: size-adaptive bitonic sort + decode + compact ----
        unsigned long long* skey = (unsigned long long*)dyn;   // 16KB
        const int csel = small_lvl ? n : min(g_ccnt[ilp], COLLCAP);
        for (int t = tid; t < COLLCAP; t += 1024)
            skey[t] = (t < csel) ? g_coll[il * COLLCAP + t] : 0ull;
        __syncthreads();

        int sortN = 512;
        while (sortN < csel) sortN <<= 1;   // <= 2048
        const int npairs = sortN >> 1;
        for (int k2 = 2; k2 <= sortN; k2 <<= 1) {
            for (int j = k2 >> 1; j > 0; j >>= 1) {
                if (tid < npairs) {
                    int i2 = ((tid & ~(j - 1)) << 1) | (tid & (j - 1));
                    int p2 = i2 + j;
                    bool dir = ((i2 & k2) == 0);
                    unsigned long long A = skey[i2], B = skey[p2];
                    if ((A > B) == dir) { skey[i2] = B; skey[p2] = A; }
                }
                __syncthreads();
            }
        }

        bool flag = false;
        float4 obox = make_float4(0.f, 0.f, 0.f, 0.f);
        float area = 0.f, score = 0.f;
        if (tid < k) {
            unsigned long long kk = skey[sortN - 1 - tid];
            int i = 131071 - (int)(kk & 0x1FFFFull);
            int r = base + i;
            const float o = mono_inv((unsigned)(kk >> 17));
            score = __fdiv_rn(1.0f, __fadd_rn(1.0f, expf(-o)));

            float4 a = *(const float4*)(anchors + 4 * r);
            const float wa = __fsub_rn(a.z, a.x);
            const float ha = __fsub_rn(a.w, a.y);
            const float cxa = __fadd_rn(a.x, __fmul_rn(0.5f, wa));
            const float cya = __fadd_rn(a.y, __fmul_rn(0.5f, ha));

            float4 d = *(const float4*)(deltas + (size_t)(img * R_TOT + r) * 4);
            const float dw = fminf(d.z, BBOX_CLIP);
            const float dh = fminf(d.w, BBOX_CLIP);
            const float cx = __fadd_rn(__fmul_rn(d.x, wa), cxa);
            const float cy = __fadd_rn(__fmul_rn(d.y, ha), cya);
            const float w = __fmul_rn(expf(dw), wa);
            const float h = __fmul_rn(expf(dh), ha);

            float x1 = __fsub_rn(cx, __fmul_rn(0.5f, w));
            float y1 = __fsub_rn(cy, __fmul_rn(0.5f, h));
            float x2 = __fadd_rn(cx, __fmul_rn(0.5f, w));
            float y2 = __fadd_rn(cy, __fmul_rn(0.5f, h));
            x1 = fminf(fmaxf(x1, 0.0f), IMG_MAX);
            y1 = fminf(fmaxf(y1, 0.0f), IMG_MAX);
            x2 = fminf(fmaxf(x2, 0.0f), IMG_MAX);
            y2 = fminf(fmaxf(y2, 0.0f), IMG_MAX);

            flag = (__fsub_rn(x2, x1) >= MIN_SIZE) &&
                   (__fsub_rn(y2, y1) >= MIN_SIZE) &&
                   (score >= 0.0f);
            g_rawbox[il * 1024 + tid] = make_float4(x1, y1, x2, y2);
            g_rawsc [il * 1024 + tid] = score;

            const float off = (float)lvl * 801.0f;
            float ox1 = __fadd_rn(x1, off);
            float oy1 = __fadd_rn(y1, off);
            float ox2 = __fadd_rn(x2, off);
            float oy2 = __fadd_rn(y2, off);
            obox = make_float4(ox1, oy1, ox2, oy2);
            area = __fmul_rn(__fsub_rn(ox2, ox1), __fsub_rn(oy2, oy1));
        }
        int m0;
        int pos = block_scan_flag(flag, &m0);
        if (flag) {
            const int gb = il * 1024 + pos;
            g_nbox [gb] = obox;
            g_narea[gb] = area;
            const int gpos = lvl * 1000 + tid;
            g_nkey [gb] = ((unsigned long long)mono_key(score) << 13) | (unsigned)(8191 - gpos);
            g_npos [gb] = tid;
        }
        if (tid == 0) g_ncnt[il] = m0;
        __syncthreads();
        if (tid == 0) flag_release_and_consume(&g_phaseC[ilp], &g_consC[ilp], nblk);
    } else {
        if (tid == 0) flag_wait_and_consume(&g_phaseC[ilp], &g_consC[ilp], nblk);
    }
    __syncthreads();

    // ================= Phase D: build bit-matrix (all nblk blocks) ==============
    float4* sbox  = (float4*)dyn;            // 16KB
    float*  sarea = (float*)(dyn + 16384);   // 4KB
    const int m = g_ncnt[il];
    for (int i = tid; i < m; i += 1024) {
        sbox[i]  = g_nbox [il * 1024 + i];
        sarea[i] = g_narea[il * 1024 + i];
    }
    __syncthreads();

    const int nch32 = (m + 31) >> 5;
    const int W64   = (nch32 + 1) >> 1;
    unsigned long long* gm64 = &g_mask64[il * 16384];
    for (int i = b * 32 + wrp; i < m; i += nblk * 32) {
        const float4 bi2 = sbox[i];
        const float ai = sarea[i];
        for (int w = (i >> 6) << 1; w < nch32; ++w) {
            const int j = (w << 5) + lane;
            bool sup = false;
            if (j > i && j < m) {
                float4 bj = sbox[j];
                float lx = fmaxf(bi2.x, bj.x), ly = fmaxf(bi2.y, bj.y);
                float rx = fminf(bi2.z, bj.z), ry = fminf(bi2.w, bj.w);
                float wx = fmaxf(__fsub_rn(rx, lx), 0.0f);
                float wy = fmaxf(__fsub_rn(ry, ly), 0.0f);
                float inter = __fmul_rn(wx, wy);
                if (inter > 0.0f) {
                    float denom = __fadd_rn(__fsub_rn(__fadd_rn(ai, sarea[j]), inter), 1e-9f);
                    float iou = __fdiv_rn(inter, denom);
                    sup = iou > NMS_THRESH;
                }
            }
            unsigned bits = __ballot_sync(0xffffffffu, sup);
            if (lane == 0) {
                unsigned* hw = (unsigned*)&gm64[(w >> 1) * 1024 + i];
                hw[w & 1] = bits;
            }
        }
    }
    __syncthreads();
    __shared__ int s_lastD;
    if (tid == 0) {
        __threadfence();
        int t3 = atomicAdd(&g_tkD[ilp], 1);
        s_lastD = (t3 == nblk - 1);
        if (s_lastD) g_tkD[ilp] = 0;
    }
    __syncthreads();
    if (!s_lastD) return;
    if (tid == 0) __threadfence();   // acquire other blocks' mask writes
    __syncthreads();

    // ================= Phase E: resolve (this block; mask in SMEM, 64-chunks) ===
    unsigned long long* sm = (unsigned long long*)dyn;   // [16][1024] = 128KB
    for (int t = tid; t < W64 * 1024; t += 1024) sm[t] = gm64[t];
    __shared__ unsigned long long ssup[16];
    __shared__ unsigned long long skept[16];
    if (tid < 16) { ssup[tid] = 0ull; skept[tid] = 0ull; }
    __syncthreads();

    for (int c = 0; c < W64; ++c) {
        if (tid == 0) {
            unsigned long long sup = ssup[c];
            unsigned long long kept = 0ull;
            const int jmax = min(64, m - (c << 6));
            const unsigned long long* dp = &sm[c * 1024 + (c << 6)];
            for (int g = 0; g < jmax; g += 8) {
                unsigned long long d0 = dp[g+0], d1 = dp[g+1], d2 = dp[g+2], d3 = dp[g+3];
                unsigned long long d4 = dp[g+4], d5 = dp[g+5], d6 = dp[g+6], d7 = dp[g+7];
                #pragma unroll
                for (int j2 = 0; j2 < 8; ++j2) {
                    const int j = g + j2;
                    if (j < jmax && !((sup >> j) & 1ull)) {
                        kept |= 1ull << j;
                        unsigned long long dj;
                        switch (j2) {
                            case 0: dj = d0; break; case 1: dj = d1; break;
                            case 2: dj = d2; break; case 3: dj = d3; break;
                            case 4: dj = d4; break; case 5: dj = d5; break;
                            case 6: dj = d6; break; default: dj = d7; break;
                        }
                        sup |= dj;
                    }
                }
            }
            skept[c] = kept;
        }
        __syncthreads();
        const int wfut = c + 1 + wrp;
        if (wfut < W64) {
            const unsigned long long kept = skept[c];
            unsigned long long v = 0ull;
            const int r1 = lane, r2 = lane + 32;
            if ((kept >> r1) & 1ull) v  = sm[wfut * 1024 + (c << 6) + r1];
            if ((kept >> r2) & 1ull) v |= sm[wfut * 1024 + (c << 6) + r2];
            #pragma unroll
            for (int d = 16; d > 0; d >>= 1)
                v |= __shfl_down_sync(0xffffffffu, v, d);
            if (lane == 0) ssup[wfut] |= v;
        }
        __syncthreads();
    }

    bool kf = (tid < m) && ((skept[tid >> 6] >> (tid & 63)) & 1ull);
    int mkept;
    int kpos = block_scan_flag(kf, &mkept);
    if (kf) {
        g_kept_key[il * 1024 + kpos] = g_nkey[il * 1024 + tid];
        g_kept_p  [il * 1024 + kpos] = g_npos[il * 1024 + tid];
    }
    if (tid == 0) g_kept_cnt[il] = mkept;
    __syncthreads();

    __shared__ int s_lastE;
    if (tid == 0) {
        __threadfence();
        int t4 = atomicAdd(&g_tkE[img * PD], 1);
        s_lastE = (t4 == N_LVL - 1);
        if (s_lastE) g_tkE[img * PD] = 0;
    }
    __syncthreads();
    if (!s_lastE) return;
    if (tid == 0) __threadfence();   // acquire all 5 kept lists
    __syncthreads();

    // ================= Phase F: merge-rank + output (1 block/image) ============
    unsigned long long* skeys = (unsigned long long*)dyn;   // 40KB
    __shared__ int cnt[N_LVL];
    if (tid < N_LVL) cnt[tid] = g_kept_cnt[img * N_LVL + tid];
    __syncthreads();
    for (int l = 0; l < N_LVL; ++l)
        for (int i = tid; i < cnt[l]; i += 1024)
            skeys[l * 1024 + i] = g_kept_key[(img * N_LVL + l) * 1024 + i];
    __syncthreads();

    float* out_b = out + img * (POST_NMS * 4);
    float* out_s = out + N_IMG * POST_NMS * 4 + img * POST_NMS;
    for (int r = tid; r < POST_NMS; r += 1024) {
        out_b[r * 4 + 0] = 0.0f;
        out_b[r * 4 + 1] = 0.0f;
        out_b[r * 4 + 2] = 0.0f;
        out_b[r * 4 + 3] = 0.0f;
        out_s[r] = -1.0f;
    }
    __syncthreads();

    for (int l = 0; l < N_LVL; ++l) {
        const int c2 = cnt[l];
        for (int i = tid; i < c2; i += 1024) {
            const unsigned long long key = skeys[l * 1024 + i];
            int rank = i;
            #pragma unroll
            for (int L2 = 0; L2 < N_LVL; ++L2) {
                if (L2 == l) continue;
                const unsigned long long* a = &skeys[L2 * 1024];
                int lo = 0, hi = cnt[L2];
                while (lo < hi) {
                    int mid = (lo + hi) >> 1;
                    if (a[mid] > key) lo = mid + 1; else hi = mid;
                }
                rank += lo;
            }
            if (rank < POST_NMS) {
                const int p = g_kept_p[(img * N_LVL + l) * 1024 + i];
                float4 bx = g_rawbox[(img * N_LVL + l) * 1024 + p];
                out_b[rank * 4 + 0] = bx.x;
                out_b[rank * 4 + 1] = bx.y;
                out_b[rank * 4 + 2] = bx.z;
                out_b[rank * 4 + 3] = bx.w;
                out_s[rank] = g_rawsc[(img * N_LVL + l) * 1024 + p];
            }
        }
    }
}

// ---------------- launch -----------------------------------------------------
extern "C" void kernel_launch(void* const* d_in, const int* in_sizes, int n_in,
                              void* d_out, int out_size) {
    const float* objectness = (const float*)d_in[0];   // [2, 159882]
    const float* deltas     = (const float*)d_in[1];   // [2, 159882, 4]
    const float* anchors    = (const float*)d_in[2];   // [159882, 4]
    float* out = (float*)d_out;                        // boxes [2,1000,4] ++ scores [2,1000]

    cudaFuncSetAttribute(rpn_kernel, cudaFuncAttributeMaxDynamicSharedMemorySize, DYN_BYTES);
    rpn_kernel<<<GRID_TOT, 1024, DYN_BYTES>>>(objectness, deltas, anchors, out);
}